// round 1
// baseline (speedup 1.0000x reference)
#include <cuda_runtime.h>

#define MAXV 100000
#define MAXE 300000
#define MAXB 16
#define MAXN (MAXB * MAXV)

// ---- scratch (static __device__ per harness rules; ~206MB) ----
__device__ int   g_cnt[MAXV];
__device__ int   g_cur[MAXV];
__device__ int   g_rowptr[MAXV + 1];
__device__ int   g_col[MAXE];
__device__ float g_w[MAXE];
__device__ float g_dinv[MAXV];
__device__ float g_h1[(size_t)MAXN * 16];
__device__ float g_h2[(size_t)MAXN * 16];

// ---------------- CSR build ----------------
__global__ void zero_kernel(int V) {
    int i = blockIdx.x * blockDim.x + threadIdx.x;
    if (i < V) { g_cnt[i] = 0; g_cur[i] = 0; }
}

__global__ void count_kernel(const int* __restrict__ edges, int E) {
    int e = blockIdx.x * blockDim.x + threadIdx.x;
    if (e < E) atomicAdd(&g_cnt[edges[2 * e + 1]], 1);
}

__global__ void dinv_kernel(int V) {
    int v = blockIdx.x * blockDim.x + threadIdx.x;
    if (v < V) g_dinv[v] = rsqrtf((float)g_cnt[v] + 1.0f);  // +1 self-loop
}

// single-block exclusive scan over g_cnt -> g_rowptr (V up to 100k: ~98 chunks)
__global__ void scan_kernel(int V) {
    __shared__ int sh[1024];
    __shared__ int carry_s;
    int t = threadIdx.x;
    if (t == 0) carry_s = 0;
    __syncthreads();
    for (int base = 0; base < V; base += 1024) {
        int i = base + t;
        int val = (i < V) ? g_cnt[i] : 0;
        sh[t] = val;
        __syncthreads();
        for (int off = 1; off < 1024; off <<= 1) {
            int add = (t >= off) ? sh[t - off] : 0;
            __syncthreads();
            sh[t] += add;
            __syncthreads();
        }
        int incl = sh[t];
        if (i < V) g_rowptr[i] = carry_s + incl - val;
        __syncthreads();
        if (t == 0) carry_s += sh[1023];
        __syncthreads();
    }
    if (t == 0) g_rowptr[V] = carry_s;
}

__global__ void scatter_kernel(const int* __restrict__ edges, int E) {
    int e = blockIdx.x * blockDim.x + threadIdx.x;
    if (e < E) {
        int s = edges[2 * e];
        int d = edges[2 * e + 1];
        int pos = g_rowptr[d] + atomicAdd(&g_cur[d], 1);
        g_col[pos] = s;
        g_w[pos] = g_dinv[s] * g_dinv[d];
    }
}

// ---------------- GCN layers (aggregate-then-transform) ----------------
// Layer 1: x(N,3) -> h1(N,16), leaky relu. One thread per node.
__global__ void layer1_kernel(const float* __restrict__ x,
                              const float* __restrict__ W1,
                              const float* __restrict__ b1,
                              int V, int N) {
    __shared__ float sW[48], sb[16];
    if (threadIdx.x < 48) sW[threadIdx.x] = W1[threadIdx.x];
    if (threadIdx.x < 16) sb[threadIdx.x] = b1[threadIdx.x];
    __syncthreads();
    int n = blockIdx.x * blockDim.x + threadIdx.x;
    if (n >= N) return;
    int v = n % V;
    int base = n - v;  // batch offset in node ids
    float di = g_dinv[v];
    float sw = di * di;
    const float* xr = x + 3 * n;
    float a0 = sw * xr[0], a1 = sw * xr[1], a2 = sw * xr[2];
    int r1 = g_rowptr[v + 1];
    for (int j = g_rowptr[v]; j < r1; j++) {
        int s = base + g_col[j];
        float w = g_w[j];
        const float* xs = x + 3 * s;
        a0 += w * xs[0];
        a1 += w * xs[1];
        a2 += w * xs[2];
    }
    float o[16];
#pragma unroll
    for (int c = 0; c < 16; c++) {
        float tv = sb[c] + a0 * sW[c] + a1 * sW[16 + c] + a2 * sW[32 + c];
        o[c] = tv > 0.f ? tv : 0.01f * tv;
    }
    float4* dst = (float4*)(g_h1 + (size_t)n * 16);
    dst[0] = make_float4(o[0], o[1], o[2], o[3]);
    dst[1] = make_float4(o[4], o[5], o[6], o[7]);
    dst[2] = make_float4(o[8], o[9], o[10], o[11]);
    dst[3] = make_float4(o[12], o[13], o[14], o[15]);
}

// Layer 2: h1(N,16) -> h2(N,16), leaky relu. 16 threads per node (coalesced 64B gathers).
__global__ void layer2_kernel(const float* __restrict__ W2,
                              const float* __restrict__ b2,
                              int V, int N) {
    __shared__ float sW[256], sb[16];
    int t = threadIdx.x;
    sW[t] = W2[t];
    if (t < 16) sb[t] = b2[t];
    __syncthreads();
    int c = t & 15;
    int n = blockIdx.x * 16 + (t >> 4);
    if (n >= N) return;
    int v = n % V;
    int base16 = (n - v) * 16;
    float di = g_dinv[v];
    float agg = di * di * g_h1[(size_t)n * 16 + c];
    int r1 = g_rowptr[v + 1];
    for (int j = g_rowptr[v]; j < r1; j++)
        agg += g_w[j] * g_h1[(size_t)base16 + g_col[j] * 16 + c];
    unsigned mask = 0xFFFFu << (t & 16);
    float out = sb[c];
#pragma unroll
    for (int k = 0; k < 16; k++) {
        float ak = __shfl_sync(mask, agg, k, 16);
        out += ak * sW[k * 16 + c];
    }
    g_h2[(size_t)n * 16 + c] = out > 0.f ? out : 0.01f * out;
}

// Layer 3: h2(N,16) -> offs(N,3); fused v = x + offs written straight into d_out.
__global__ void layer3_kernel(const float* __restrict__ x,
                              const float* __restrict__ W3,
                              const float* __restrict__ b3,
                              float* __restrict__ out,
                              int V, int E, int N) {
    __shared__ float sW[48], sb[3];
    int t = threadIdx.x;
    if (t < 48) sW[t] = W3[t];
    if (t < 3) sb[t] = b3[t];
    __syncthreads();
    int c = t & 15;
    int n = blockIdx.x * 16 + (t >> 4);
    if (n >= N) return;
    int v = n % V;
    int b = n / V;
    int base16 = (n - v) * 16;
    float di = g_dinv[v];
    float agg = di * di * g_h2[(size_t)n * 16 + c];
    int r1 = g_rowptr[v + 1];
    for (int j = g_rowptr[v]; j < r1; j++)
        agg += g_w[j] * g_h2[(size_t)base16 + g_col[j] * 16 + c];
    unsigned mask = 0xFFFFu << (t & 16);
    float vals[3];
#pragma unroll
    for (int cp = 0; cp < 3; cp++) {
        float val = agg * sW[c * 3 + cp];
        val += __shfl_down_sync(mask, val, 8, 16);
        val += __shfl_down_sync(mask, val, 4, 16);
        val += __shfl_down_sync(mask, val, 2, 16);
        val += __shfl_down_sync(mask, val, 1, 16);
        vals[cp] = val;
    }
    if (c == 0) {
        size_t o = ((size_t)b * (V + E) + v) * 3;
        out[o + 0] = sb[0] + vals[0] + x[(size_t)n * 3 + 0];
        out[o + 1] = sb[1] + vals[1] + x[(size_t)n * 3 + 1];
        out[o + 2] = sb[2] + vals[2] + x[(size_t)n * 3 + 2];
    }
}

// Midpoints: mid[b][e] = (v[b][src] + v[b][dst]) / 2
__global__ void mid_kernel(const int* __restrict__ edges, float* __restrict__ out,
                           int V, int E, int B) {
    int i = blockIdx.x * blockDim.x + threadIdx.x;
    int total = B * E;
    if (i >= total) return;
    int e = i % E, b = i / E;
    int s = edges[2 * e], d = edges[2 * e + 1];
    const float* vb = out + (size_t)b * (V + E) * 3;
    float* m = out + ((size_t)b * (V + E) + V + (size_t)e) * 3;
    m[0] = 0.5f * (vb[3 * s + 0] + vb[3 * d + 0]);
    m[1] = 0.5f * (vb[3 * s + 1] + vb[3 * d + 1]);
    m[2] = 0.5f * (vb[3 * s + 2] + vb[3 * d + 2]);
}

// Broadcast faces_sub across B, int32 -> float32 (exact: values < 2^24)
__global__ void faces_kernel(const int* __restrict__ faces, float* __restrict__ out,
                             int perB, int total) {
    int i = blockIdx.x * blockDim.x + threadIdx.x;
    if (i >= total) return;
    out[i] = (float)faces[i % perB];
}

extern "C" void kernel_launch(void* const* d_in, const int* in_sizes, int n_in,
                              void* d_out, int out_size) {
    const float* verts = (const float*)d_in[0];
    const int*   edges = (const int*)d_in[1];
    const int*   faces = (const int*)d_in[2];
    const float* W1 = (const float*)d_in[3];
    const float* b1 = (const float*)d_in[4];
    const float* W2 = (const float*)d_in[5];
    const float* b2 = (const float*)d_in[6];
    const float* W3 = (const float*)d_in[7];
    const float* b3 = (const float*)d_in[8];
    float* out = (float*)d_out;

    const int B = 16;
    int E = in_sizes[1] / 2;
    int Fsub = in_sizes[2] / 3;
    int V = in_sizes[0] / (B * 3);
    int N = B * V;

    // CSR build (per-batch graph is identical; build once over V,E)
    zero_kernel<<<(V + 255) / 256, 256>>>(V);
    count_kernel<<<(E + 255) / 256, 256>>>(edges, E);
    dinv_kernel<<<(V + 255) / 256, 256>>>(V);
    scan_kernel<<<1, 1024>>>(V);
    scatter_kernel<<<(E + 255) / 256, 256>>>(edges, E);

    // GCN layers
    layer1_kernel<<<(N + 255) / 256, 256>>>(verts, W1, b1, V, N);
    layer2_kernel<<<(N + 15) / 16, 256>>>(W2, b2, V, N);
    layer3_kernel<<<(N + 15) / 16, 256>>>(verts, W3, b3, out, V, E, N);

    // Midpoints + faces
    mid_kernel<<<(B * E + 255) / 256, 256>>>(edges, out, V, E, B);

    long long vertsOut = (long long)B * (V + E) * 3;
    long long facesOut = (long long)B * Fsub * 3;
    if ((long long)out_size >= vertsOut + facesOut) {
        faces_kernel<<<(int)((facesOut + 255) / 256), 256>>>(
            faces, out + vertsOut, Fsub * 3, (int)facesOut);
    }
}

// round 3
// speedup vs baseline: 1.3732x; 1.3732x over previous
#include <cuda_runtime.h>

#define MAXV 100000
#define MAXE 300000
#define MAXB 16
#define MAXN (MAXB * MAXV)

// ---- scratch (static __device__ per harness rules) ----
__device__ int    g_cnt[MAXV];
__device__ int    g_cur[MAXV];
__device__ int    g_rowptr[MAXV + 1];
__device__ int    g_part[128];
__device__ int    g_col[MAXE];
__device__ float  g_w[MAXE];
__device__ float  g_dinv[MAXV];
__device__ float4 g_x4[MAXN];   // padded input verts (one 16B gather per neighbor)
__device__ float4 g_v4[MAXN];   // padded displaced verts for the mid kernel
__device__ float  g_h1[(size_t)MAXN * 16];
__device__ float  g_h2[(size_t)MAXN * 16];

// ---------------- CSR build ----------------
__global__ void zero_kernel(int V) {
    int i = blockIdx.x * blockDim.x + threadIdx.x;
    if (i < V) { g_cnt[i] = 0; g_cur[i] = 0; }
}

__global__ void count_kernel(const int* __restrict__ edges, int E) {
    int e = blockIdx.x * blockDim.x + threadIdx.x;
    if (e < E) atomicAdd(&g_cnt[edges[2 * e + 1]], 1);
}

__global__ void dinv_kernel(int V) {
    int v = blockIdx.x * blockDim.x + threadIdx.x;
    if (v < V) g_dinv[v] = rsqrtf((float)g_cnt[v] + 1.0f);  // +1 self-loop
}

// 3-pass scan: per-block scan + partials, scan partials, add offsets.
__global__ void scanA_kernel(int V) {
    __shared__ int sh[1024];
    int t = threadIdx.x;
    int i = blockIdx.x * 1024 + t;
    int val = (i < V) ? g_cnt[i] : 0;
    sh[t] = val;
    __syncthreads();
    for (int off = 1; off < 1024; off <<= 1) {
        int add = (t >= off) ? sh[t - off] : 0;
        __syncthreads();
        sh[t] += add;
        __syncthreads();
    }
    if (i < V) g_rowptr[i] = sh[t] - val;  // exclusive, pre-carry
    if (t == 1023) g_part[blockIdx.x] = sh[1023];
}

__global__ void scanB_kernel(int nblocks, int V) {
    __shared__ int sh[128];
    int t = threadIdx.x;
    int val = (t < nblocks) ? g_part[t] : 0;
    sh[t] = val;
    __syncthreads();
    for (int off = 1; off < 128; off <<= 1) {
        int add = (t >= off) ? sh[t - off] : 0;
        __syncthreads();
        sh[t] += add;
        __syncthreads();
    }
    g_part[t] = sh[t] - val;  // exclusive block offsets
    if (t == 127) g_rowptr[V] = sh[127];
}

__global__ void scanC_kernel(int V) {
    int i = blockIdx.x * blockDim.x + threadIdx.x;
    if (i < V) g_rowptr[i] += g_part[i >> 10];
}

__global__ void scatter_kernel(const int* __restrict__ edges, int E) {
    int e = blockIdx.x * blockDim.x + threadIdx.x;
    if (e < E) {
        int s = edges[2 * e];
        int d = edges[2 * e + 1];
        int pos = g_rowptr[d] + atomicAdd(&g_cur[d], 1);
        g_col[pos] = s;
        g_w[pos] = g_dinv[s] * g_dinv[d];
    }
}

// Pad input verts into float4 layout for single-sector gathers.
__global__ void pad_kernel(const float* __restrict__ x, int N) {
    int n = blockIdx.x * blockDim.x + threadIdx.x;
    if (n < N) {
        const float* p = x + (size_t)n * 3;
        g_x4[n] = make_float4(p[0], p[1], p[2], 0.f);
    }
}

// ---------------- GCN layers (aggregate-then-transform) ----------------
// Layer 1: x(N,3) -> h1(N,16), leaky relu. One thread per node, float4 gathers.
__global__ void layer1_kernel(const float* __restrict__ W1,
                              const float* __restrict__ b1,
                              int V, int N) {
    __shared__ float sW[48], sb[16];
    if (threadIdx.x < 48) sW[threadIdx.x] = W1[threadIdx.x];
    if (threadIdx.x < 16) sb[threadIdx.x] = b1[threadIdx.x];
    __syncthreads();
    int n = blockIdx.x * blockDim.x + threadIdx.x;
    if (n >= N) return;
    int v = n % V;
    int base = n - v;  // batch offset in node ids
    float di = g_dinv[v];
    float sw = di * di;
    float4 xr = g_x4[n];
    float a0 = sw * xr.x, a1 = sw * xr.y, a2 = sw * xr.z;
    int r1 = g_rowptr[v + 1];
    for (int j = g_rowptr[v]; j < r1; j++) {
        float w = g_w[j];
        float4 xs = g_x4[base + g_col[j]];
        a0 += w * xs.x;
        a1 += w * xs.y;
        a2 += w * xs.z;
    }
    float o[16];
#pragma unroll
    for (int c = 0; c < 16; c++) {
        float tv = sb[c] + a0 * sW[c] + a1 * sW[16 + c] + a2 * sW[32 + c];
        o[c] = tv > 0.f ? tv : 0.01f * tv;
    }
    float4* dst = (float4*)(g_h1 + (size_t)n * 16);
    dst[0] = make_float4(o[0], o[1], o[2], o[3]);
    dst[1] = make_float4(o[4], o[5], o[6], o[7]);
    dst[2] = make_float4(o[8], o[9], o[10], o[11]);
    dst[3] = make_float4(o[12], o[13], o[14], o[15]);
}

// Layer 2: h1(N,16) -> h2(N,16), leaky relu. 16 threads per node (coalesced 64B gathers).
__global__ void layer2_kernel(const float* __restrict__ W2,
                              const float* __restrict__ b2,
                              int V, int N) {
    __shared__ float sW[256], sb[16];
    int t = threadIdx.x;
    sW[t] = W2[t];
    if (t < 16) sb[t] = b2[t];
    __syncthreads();
    int c = t & 15;
    int n = blockIdx.x * 16 + (t >> 4);
    if (n >= N) return;
    int v = n % V;
    int base16 = (n - v) * 16;
    float di = g_dinv[v];
    float agg = di * di * g_h1[(size_t)n * 16 + c];
    int r1 = g_rowptr[v + 1];
    for (int j = g_rowptr[v]; j < r1; j++)
        agg += g_w[j] * g_h1[(size_t)base16 + g_col[j] * 16 + c];
    unsigned mask = 0xFFFFu << (t & 16);
    float out = sb[c];
#pragma unroll
    for (int k = 0; k < 16; k++) {
        float ak = __shfl_sync(mask, agg, k, 16);
        out += ak * sW[k * 16 + c];
    }
    g_h2[(size_t)n * 16 + c] = out > 0.f ? out : 0.01f * out;
}

// Layer 3: h2(N,16) -> offs(N,3); fused v = x + offs; writes d_out AND g_v4.
__global__ void layer3_kernel(const float* __restrict__ W3,
                              const float* __restrict__ b3,
                              float* __restrict__ out,
                              int V, int E, int N) {
    __shared__ float sW[48], sb[3];
    int t = threadIdx.x;
    if (t < 48) sW[t] = W3[t];
    if (t < 3) sb[t] = b3[t];
    __syncthreads();
    int c = t & 15;
    int n = blockIdx.x * 16 + (t >> 4);
    if (n >= N) return;
    int v = n % V;
    int b = n / V;
    int base16 = (n - v) * 16;
    float di = g_dinv[v];
    float agg = di * di * g_h2[(size_t)n * 16 + c];
    int r1 = g_rowptr[v + 1];
    for (int j = g_rowptr[v]; j < r1; j++)
        agg += g_w[j] * g_h2[(size_t)base16 + g_col[j] * 16 + c];
    unsigned mask = 0xFFFFu << (t & 16);
    float vals[3];
#pragma unroll
    for (int cp = 0; cp < 3; cp++) {
        float val = agg * sW[c * 3 + cp];
        val += __shfl_down_sync(mask, val, 8, 16);
        val += __shfl_down_sync(mask, val, 4, 16);
        val += __shfl_down_sync(mask, val, 2, 16);
        val += __shfl_down_sync(mask, val, 1, 16);
        vals[cp] = val;
    }
    if (c == 0) {
        float4 xr = g_x4[n];
        float vx = sb[0] + vals[0] + xr.x;
        float vy = sb[1] + vals[1] + xr.y;
        float vz = sb[2] + vals[2] + xr.z;
        size_t o = ((size_t)b * (V + E) + v) * 3;
        out[o + 0] = vx;
        out[o + 1] = vy;
        out[o + 2] = vz;
        g_v4[n] = make_float4(vx, vy, vz, 0.f);
    }
}

// Midpoints: mid[b][e] = (v[b][src] + v[b][dst]) / 2. 2D grid, float4 gathers.
__global__ void mid_kernel(const int* __restrict__ edges, float* __restrict__ out,
                           int V, int E) {
    int e = blockIdx.x * blockDim.x + threadIdx.x;
    if (e >= E) return;
    int b = blockIdx.y;
    int s = edges[2 * e], d = edges[2 * e + 1];
    int base = b * V;
    float4 vs = g_v4[base + s];
    float4 vd = g_v4[base + d];
    float* m = out + ((size_t)b * (V + E) + V + (size_t)e) * 3;
    m[0] = 0.5f * (vs.x + vd.x);
    m[1] = 0.5f * (vs.y + vd.y);
    m[2] = 0.5f * (vs.z + vd.z);
}

// Broadcast faces_sub across B, int32 -> float32 (exact below 2^24).
// Each thread reads once, writes all B batch copies.
__global__ void faces_kernel(const int* __restrict__ faces, float* __restrict__ out,
                             int perB, int B) {
    int i = blockIdx.x * blockDim.x + threadIdx.x;
    if (i >= perB) return;
    float f = (float)faces[i];
#pragma unroll
    for (int b = 0; b < MAXB; b++) {
        if (b < B) out[(size_t)b * perB + i] = f;
    }
}

extern "C" void kernel_launch(void* const* d_in, const int* in_sizes, int n_in,
                              void* d_out, int out_size) {
    const float* verts = (const float*)d_in[0];
    const int*   edges = (const int*)d_in[1];
    const int*   faces = (const int*)d_in[2];
    const float* W1 = (const float*)d_in[3];
    const float* b1 = (const float*)d_in[4];
    const float* W2 = (const float*)d_in[5];
    const float* b2 = (const float*)d_in[6];
    const float* W3 = (const float*)d_in[7];
    const float* b3 = (const float*)d_in[8];
    float* out = (float*)d_out;

    const int B = 16;
    int E = in_sizes[1] / 2;
    int Fsub = in_sizes[2] / 3;
    int V = in_sizes[0] / (B * 3);
    int N = B * V;
    int nScanBlocks = (V + 1023) / 1024;

    // CSR build (per-batch graph identical; build once over V,E)
    zero_kernel<<<(V + 255) / 256, 256>>>(V);
    count_kernel<<<(E + 255) / 256, 256>>>(edges, E);
    dinv_kernel<<<(V + 255) / 256, 256>>>(V);
    scanA_kernel<<<nScanBlocks, 1024>>>(V);
    scanB_kernel<<<1, 128>>>(nScanBlocks, V);
    scanC_kernel<<<(V + 255) / 256, 256>>>(V);
    scatter_kernel<<<(E + 255) / 256, 256>>>(edges, E);
    pad_kernel<<<(N + 255) / 256, 256>>>(verts, N);

    // GCN layers
    layer1_kernel<<<(N + 255) / 256, 256>>>(W1, b1, V, N);
    layer2_kernel<<<(N + 15) / 16, 256>>>(W2, b2, V, N);
    layer3_kernel<<<(N + 15) / 16, 256>>>(W3, b3, out, V, E, N);

    // Midpoints
    dim3 midGrid((E + 255) / 256, B);
    mid_kernel<<<midGrid, 256>>>(edges, out, V, E);

    // Faces broadcast
    long long vertsOut = (long long)B * (V + E) * 3;
    long long facesOut = (long long)B * Fsub * 3;
    if ((long long)out_size >= vertsOut + facesOut) {
        faces_kernel<<<(Fsub * 3 + 255) / 256, 256>>>(
            faces, out + vertsOut, Fsub * 3, B);
    }
}

// round 5
// speedup vs baseline: 1.4496x; 1.0557x over previous
#include <cuda_runtime.h>
#include <cuda_fp16.h>

#define MAXV 100000
#define MAXE 300000
#define MAXB 16
#define MAXN (MAXB * MAXV)

// ---- scratch (static __device__ per harness rules) ----
__device__ int    g_cnt[MAXV];
__device__ int    g_cur[MAXV];
__device__ int    g_rowptr[MAXV + 1];
__device__ int    g_part[128];
__device__ int    g_col[MAXE];
__device__ float  g_w[MAXE];
__device__ float  g_dinv[MAXV];
__device__ __align__(8)  __half2 g_xh[MAXN][2];            // packed half xyz (8B/node)
__device__ float4 g_v4[MAXN];                              // displaced verts (fp32: output-critical)
__device__ __align__(16) __half  g_h1[(size_t)MAXN * 16];  // half intermediates
__device__ __align__(16) __half  g_h2[(size_t)MAXN * 16];

// ---------------- CSR build ----------------
__global__ void zero_kernel(int V) {
    int i = blockIdx.x * blockDim.x + threadIdx.x;
    if (i < V) { g_cnt[i] = 0; g_cur[i] = 0; }
}

__global__ void count_kernel(const int* __restrict__ edges, int E) {
    int e = blockIdx.x * blockDim.x + threadIdx.x;
    if (e < E) atomicAdd(&g_cnt[edges[2 * e + 1]], 1);
}

__global__ void dinv_kernel(int V) {
    int v = blockIdx.x * blockDim.x + threadIdx.x;
    if (v < V) g_dinv[v] = rsqrtf((float)g_cnt[v] + 1.0f);  // +1 self-loop
}

// 3-pass scan
__global__ void scanA_kernel(int V) {
    __shared__ int sh[1024];
    int t = threadIdx.x;
    int i = blockIdx.x * 1024 + t;
    int val = (i < V) ? g_cnt[i] : 0;
    sh[t] = val;
    __syncthreads();
    for (int off = 1; off < 1024; off <<= 1) {
        int add = (t >= off) ? sh[t - off] : 0;
        __syncthreads();
        sh[t] += add;
        __syncthreads();
    }
    if (i < V) g_rowptr[i] = sh[t] - val;
    if (t == 1023) g_part[blockIdx.x] = sh[1023];
}

__global__ void scanB_kernel(int nblocks, int V) {
    __shared__ int sh[128];
    int t = threadIdx.x;
    int val = (t < nblocks) ? g_part[t] : 0;
    sh[t] = val;
    __syncthreads();
    for (int off = 1; off < 128; off <<= 1) {
        int add = (t >= off) ? sh[t - off] : 0;
        __syncthreads();
        sh[t] += add;
        __syncthreads();
    }
    g_part[t] = sh[t] - val;
    if (t == 127) g_rowptr[V] = sh[127];
}

__global__ void scanC_kernel(int V) {
    int i = blockIdx.x * blockDim.x + threadIdx.x;
    if (i < V) g_rowptr[i] += g_part[i >> 10];
}

__global__ void scatter_kernel(const int* __restrict__ edges, int E) {
    int e = blockIdx.x * blockDim.x + threadIdx.x;
    if (e < E) {
        int s = edges[2 * e];
        int d = edges[2 * e + 1];
        int pos = g_rowptr[d] + atomicAdd(&g_cur[d], 1);
        g_col[pos] = s;
        g_w[pos] = g_dinv[s] * g_dinv[d];
    }
}

// Pack input verts into half (8B/node): one-sector gathers in layer1.
__global__ void pad_kernel(const float* __restrict__ x, int N) {
    int n = blockIdx.x * blockDim.x + threadIdx.x;
    if (n < N) {
        const float* p = x + (size_t)n * 3;
        g_xh[n][0] = __floats2half2_rn(p[0], p[1]);
        g_xh[n][1] = __floats2half2_rn(p[2], 0.f);
    }
}

// ---------------- GCN layers (aggregate-then-transform) ----------------
// Layer 1: x(N,3) -> h1(N,16) half, leaky relu. One thread per node, 8B gathers.
__global__ void layer1_kernel(const float* __restrict__ W1,
                              const float* __restrict__ b1,
                              int V, int N) {
    __shared__ float sW[48], sb[16];
    if (threadIdx.x < 48) sW[threadIdx.x] = W1[threadIdx.x];
    if (threadIdx.x < 16) sb[threadIdx.x] = b1[threadIdx.x];
    __syncthreads();
    int n = blockIdx.x * blockDim.x + threadIdx.x;
    if (n >= N) return;
    int v = n % V;
    int base = n - v;
    float di = g_dinv[v];
    float sw = di * di;
    __half2 self[2];
    *(uint2*)self = *(const uint2*)g_xh[n];
    float2 s01 = __half22float2(self[0]);
    float2 s2_ = __half22float2(self[1]);
    float a0 = sw * s01.x, a1 = sw * s01.y, a2 = sw * s2_.x;
    int r1 = g_rowptr[v + 1];
    for (int j = g_rowptr[v]; j < r1; j++) {
        float w = g_w[j];
        __half2 nb[2];
        *(uint2*)nb = *(const uint2*)g_xh[base + g_col[j]];
        float2 n01 = __half22float2(nb[0]);
        float2 n2_ = __half22float2(nb[1]);
        a0 += w * n01.x;
        a1 += w * n01.y;
        a2 += w * n2_.x;
    }
    __half2 o[8];
#pragma unroll
    for (int c = 0; c < 8; c++) {
        float t0 = sb[2*c]   + a0 * sW[2*c]   + a1 * sW[16 + 2*c]   + a2 * sW[32 + 2*c];
        float t1 = sb[2*c+1] + a0 * sW[2*c+1] + a1 * sW[16 + 2*c+1] + a2 * sW[32 + 2*c+1];
        t0 = t0 > 0.f ? t0 : 0.01f * t0;
        t1 = t1 > 0.f ? t1 : 0.01f * t1;
        o[c] = __floats2half2_rn(t0, t1);
    }
    uint4* dst = (uint4*)(g_h1 + (size_t)n * 16);  // 32B, 16B-aligned
    dst[0] = ((uint4*)o)[0];
    dst[1] = ((uint4*)o)[1];
}

// Layer 2: h1 -> h2 (half), leaky relu. 16 threads/node: 32B one-sector gathers.
__global__ void layer2_kernel(const float* __restrict__ W2,
                              const float* __restrict__ b2,
                              int V, int N) {
    __shared__ float sW[256], sb[16];
    int t = threadIdx.x;
    sW[t] = W2[t];
    if (t < 16) sb[t] = b2[t];
    __syncthreads();
    int c = t & 15;
    int n = blockIdx.x * 16 + (t >> 4);
    if (n >= N) return;
    int v = n % V;
    int base16 = (n - v) * 16;
    float di = g_dinv[v];
    float agg = di * di * __half2float(g_h1[(size_t)n * 16 + c]);
    int r1 = g_rowptr[v + 1];
    for (int j = g_rowptr[v]; j < r1; j++)
        agg += g_w[j] * __half2float(g_h1[(size_t)base16 + g_col[j] * 16 + c]);
    unsigned mask = 0xFFFFu << (t & 16);
    float out = sb[c];
#pragma unroll
    for (int k = 0; k < 16; k++) {
        float ak = __shfl_sync(mask, agg, k, 16);
        out += ak * sW[k * 16 + c];
    }
    out = out > 0.f ? out : 0.01f * out;
    g_h2[(size_t)n * 16 + c] = __float2half(out);
}

// Layer 3: h2 -> offs(N,3); fused v = x + offs; writes d_out AND g_v4 (fp32).
__global__ void layer3_kernel(const float* __restrict__ x,
                              const float* __restrict__ W3,
                              const float* __restrict__ b3,
                              float* __restrict__ out,
                              int V, int E, int N) {
    __shared__ float sW[48], sb[3];
    int t = threadIdx.x;
    if (t < 48) sW[t] = W3[t];
    if (t < 3) sb[t] = b3[t];
    __syncthreads();
    int c = t & 15;
    int n = blockIdx.x * 16 + (t >> 4);
    if (n >= N) return;
    int v = n % V;
    int b = n / V;
    int base16 = (n - v) * 16;
    float di = g_dinv[v];
    float agg = di * di * __half2float(g_h2[(size_t)n * 16 + c]);
    int r1 = g_rowptr[v + 1];
    for (int j = g_rowptr[v]; j < r1; j++)
        agg += g_w[j] * __half2float(g_h2[(size_t)base16 + g_col[j] * 16 + c]);
    unsigned mask = 0xFFFFu << (t & 16);
    float vals[3];
#pragma unroll
    for (int cp = 0; cp < 3; cp++) {
        float val = agg * sW[c * 3 + cp];
        val += __shfl_down_sync(mask, val, 8, 16);
        val += __shfl_down_sync(mask, val, 4, 16);
        val += __shfl_down_sync(mask, val, 2, 16);
        val += __shfl_down_sync(mask, val, 1, 16);
        vals[cp] = val;
    }
    if (c == 0) {
        const float* xr = x + (size_t)n * 3;   // fp32 original verts (output-critical)
        float vx = sb[0] + vals[0] + xr[0];
        float vy = sb[1] + vals[1] + xr[1];
        float vz = sb[2] + vals[2] + xr[2];
        size_t o = ((size_t)b * (V + E) + v) * 3;
        out[o + 0] = vx;
        out[o + 1] = vy;
        out[o + 2] = vz;
        g_v4[n] = make_float4(vx, vy, vz, 0.f);
    }
}

// Midpoints: mid[b][e] = (v[b][src] + v[b][dst]) / 2. 2D grid, float4 gathers.
__global__ void mid_kernel(const int* __restrict__ edges, float* __restrict__ out,
                           int V, int E) {
    int e = blockIdx.x * blockDim.x + threadIdx.x;
    if (e >= E) return;
    int b = blockIdx.y;
    int s = edges[2 * e], d = edges[2 * e + 1];
    int base = b * V;
    float4 vs = g_v4[base + s];
    float4 vd = g_v4[base + d];
    float* m = out + ((size_t)b * (V + E) + V + (size_t)e) * 3;
    m[0] = 0.5f * (vs.x + vd.x);
    m[1] = 0.5f * (vs.y + vd.y);
    m[2] = 0.5f * (vs.z + vd.z);
}

// Broadcast faces across B, int32 -> float32 (exact below 2^24). Read once, write B.
__global__ void faces_kernel(const int* __restrict__ faces, float* __restrict__ out,
                             int perB, int B) {
    int i = blockIdx.x * blockDim.x + threadIdx.x;
    if (i >= perB) return;
    float f = (float)faces[i];
#pragma unroll
    for (int b = 0; b < MAXB; b++) {
        if (b < B) out[(size_t)b * perB + i] = f;
    }
}

extern "C" void kernel_launch(void* const* d_in, const int* in_sizes, int n_in,
                              void* d_out, int out_size) {
    const float* verts = (const float*)d_in[0];
    const int*   edges = (const int*)d_in[1];
    const int*   faces = (const int*)d_in[2];
    const float* W1 = (const float*)d_in[3];
    const float* b1 = (const float*)d_in[4];
    const float* W2 = (const float*)d_in[5];
    const float* b2 = (const float*)d_in[6];
    const float* W3 = (const float*)d_in[7];
    const float* b3 = (const float*)d_in[8];
    float* out = (float*)d_out;

    const int B = 16;
    int E = in_sizes[1] / 2;
    int Fsub = in_sizes[2] / 3;
    int V = in_sizes[0] / (B * 3);
    int N = B * V;
    int nScanBlocks = (V + 1023) / 1024;

    // CSR build (per-batch graph identical; build once over V,E)
    zero_kernel<<<(V + 255) / 256, 256>>>(V);
    count_kernel<<<(E + 255) / 256, 256>>>(edges, E);
    dinv_kernel<<<(V + 255) / 256, 256>>>(V);
    scanA_kernel<<<nScanBlocks, 1024>>>(V);
    scanB_kernel<<<1, 128>>>(nScanBlocks, V);
    scanC_kernel<<<(V + 255) / 256, 256>>>(V);
    scatter_kernel<<<(E + 255) / 256, 256>>>(edges, E);
    pad_kernel<<<(N + 255) / 256, 256>>>(verts, N);

    // GCN layers
    layer1_kernel<<<(N + 255) / 256, 256>>>(W1, b1, V, N);
    layer2_kernel<<<(N + 15) / 16, 256>>>(W2, b2, V, N);
    layer3_kernel<<<(N + 15) / 16, 256>>>(verts, W3, b3, out, V, E, N);

    // Midpoints
    dim3 midGrid((E + 255) / 256, B);
    mid_kernel<<<midGrid, 256>>>(edges, out, V, E);

    // Faces broadcast
    long long vertsOut = (long long)B * (V + E) * 3;
    long long facesOut = (long long)B * Fsub * 3;
    if ((long long)out_size >= vertsOut + facesOut) {
        faces_kernel<<<(Fsub * 3 + 255) / 256, 256>>>(
            faces, out + vertsOut, Fsub * 3, B);
    }
}

// round 6
// speedup vs baseline: 2.7707x; 1.9114x over previous
#include <cuda_runtime.h>
#include <cuda_fp16.h>

#define MAXV 100000
#define MAXE 300000
#define MAXB 16
#define MAXN (MAXB * MAXV)

// ---- scratch (static __device__ per harness rules) ----
__device__ int    g_cnt[MAXV];
__device__ int    g_cur[MAXV];
__device__ int    g_rowptr[MAXV + 1];
__device__ int    g_part[128];
__device__ int    g_col[MAXE];
__device__ float  g_w[MAXE];
__device__ float  g_dinv[MAXV];
__device__ __align__(16) __half g_xT[(size_t)MAXV * MAXB * 4];   // xT[v][b][0..3] half (8B/node)
__device__ float4 g_v4[MAXN];                                    // (b,v) displaced verts fp32
__device__ __align__(16) __half g_h1[(size_t)MAXV * MAXB * 16];  // h[v][b][c]
__device__ __align__(16) __half g_h2[(size_t)MAXV * MAXB * 16];

// ---------------- CSR build ----------------
__global__ void zero_kernel(int V) {
    int i = blockIdx.x * blockDim.x + threadIdx.x;
    if (i < V) { g_cnt[i] = 0; g_cur[i] = 0; }
}

__global__ void count_kernel(const int* __restrict__ edges, int E) {
    int e = blockIdx.x * blockDim.x + threadIdx.x;
    if (e < E) atomicAdd(&g_cnt[edges[2 * e + 1]], 1);
}

// scanA also produces dinv (reads g_cnt anyway)
__global__ void scanA_kernel(int V) {
    __shared__ int sh[1024];
    int t = threadIdx.x;
    int i = blockIdx.x * 1024 + t;
    int val = (i < V) ? g_cnt[i] : 0;
    if (i < V) g_dinv[i] = rsqrtf((float)val + 1.0f);  // +1 self-loop
    sh[t] = val;
    __syncthreads();
    for (int off = 1; off < 1024; off <<= 1) {
        int add = (t >= off) ? sh[t - off] : 0;
        __syncthreads();
        sh[t] += add;
        __syncthreads();
    }
    if (i < V) g_rowptr[i] = sh[t] - val;
    if (t == 1023) g_part[blockIdx.x] = sh[1023];
}

__global__ void scanB_kernel(int nblocks, int V) {
    __shared__ int sh[128];
    int t = threadIdx.x;
    int val = (t < nblocks) ? g_part[t] : 0;
    sh[t] = val;
    __syncthreads();
    for (int off = 1; off < 128; off <<= 1) {
        int add = (t >= off) ? sh[t - off] : 0;
        __syncthreads();
        sh[t] += add;
        __syncthreads();
    }
    g_part[t] = sh[t] - val;
    if (t == 127) g_rowptr[V] = sh[127];
}

__global__ void scanC_kernel(int V) {
    int i = blockIdx.x * blockDim.x + threadIdx.x;
    if (i < V) g_rowptr[i] += g_part[i >> 10];
}

__global__ void scatter_kernel(const int* __restrict__ edges, int E) {
    int e = blockIdx.x * blockDim.x + threadIdx.x;
    if (e < E) {
        int s = edges[2 * e];
        int d = edges[2 * e + 1];
        int pos = g_rowptr[d] + atomicAdd(&g_cur[d], 1);
        g_col[pos] = s;
        g_w[pos] = g_dinv[s] * g_dinv[d];
    }
}

// Transpose x(b,v,3) -> xT[v][b] packed half (8B per (v,b)).
__global__ void padT_kernel(const float* __restrict__ x, int V, int N) {
    int n = blockIdx.x * blockDim.x + threadIdx.x;
    if (n >= N) return;
    int v = n % V, b = n / V;
    const float* p = x + (size_t)n * 3;
    __half2* dst = (__half2*)(g_xT + ((size_t)v * MAXB + b) * 4);
    dst[0] = __floats2half2_rn(p[0], p[1]);
    dst[1] = __floats2half2_rn(p[2], 0.f);
}

// ---------------- GCN layers: warp per vertex, all 16 batches ----------------
// lane t = 2*b + h ; thread handles batch b, channels [8h, 8h+8)

// Layer 1: xT -> h1[v][b][c]
__global__ void layer1_kernel(const float* __restrict__ W1,
                              const float* __restrict__ b1, int V) {
    __shared__ float sW[48], sb[16];
    if (threadIdx.x < 48) sW[threadIdx.x] = W1[threadIdx.x];
    if (threadIdx.x < 16) sb[threadIdx.x] = b1[threadIdx.x];
    __syncthreads();
    int v = blockIdx.x * 8 + (threadIdx.x >> 5);
    if (v >= V) return;
    int t = threadIdx.x & 31;
    int b = t >> 1, h = t & 1;
    float di = g_dinv[v];
    float swt = di * di;

    const uint2* xrow = (const uint2*)(g_xT + ((size_t)v * MAXB + b) * 4);
    uint2 raw = *xrow;
    __half2 p0 = *(__half2*)&raw.x, p1 = *(__half2*)&raw.y;
    float2 f0 = __half22float2(p0), f1 = __half22float2(p1);
    float a0 = swt * f0.x, a1 = swt * f0.y, a2 = swt * f1.x;

    int r1 = g_rowptr[v + 1];
    for (int j = g_rowptr[v]; j < r1; j++) {
        float w = g_w[j];
        int col = g_col[j];
        uint2 nb = *(const uint2*)(g_xT + ((size_t)col * MAXB + b) * 4);
        __half2 n0 = *(__half2*)&nb.x, n1 = *(__half2*)&nb.y;
        float2 g0 = __half22float2(n0), g1 = __half22float2(n1);
        a0 += w * g0.x; a1 += w * g0.y; a2 += w * g1.x;
    }
    __half2 o[4];
#pragma unroll
    for (int i = 0; i < 4; i++) {
        int c0 = h * 8 + 2 * i, c1 = c0 + 1;
        float t0 = sb[c0] + a0 * sW[c0] + a1 * sW[16 + c0] + a2 * sW[32 + c0];
        float t1 = sb[c1] + a0 * sW[c1] + a1 * sW[16 + c1] + a2 * sW[32 + c1];
        t0 = t0 > 0.f ? t0 : 0.01f * t0;
        t1 = t1 > 0.f ? t1 : 0.01f * t1;
        o[i] = __floats2half2_rn(t0, t1);
    }
    *(uint4*)(g_h1 + (size_t)v * 256 + t * 8) = *(uint4*)o;  // 512B coalesced per warp
}

// Layer 2: h1 -> h2. One 512B coalesced load per neighbor per warp.
__global__ void layer2_kernel(const float* __restrict__ W2,
                              const float* __restrict__ b2, int V) {
    __shared__ float sW[256], sb[16];
    sW[threadIdx.x] = W2[threadIdx.x];
    if (threadIdx.x < 16) sb[threadIdx.x] = b2[threadIdx.x];
    __syncthreads();
    int v = blockIdx.x * 8 + (threadIdx.x >> 5);
    if (v >= V) return;
    int t = threadIdx.x & 31;
    int h = t & 1;
    float di = g_dinv[v];
    float swt = di * di;

    float agg[8];
    {
        uint4 raw = *(const uint4*)(g_h1 + (size_t)v * 256 + t * 8);
        __half2* hp = (__half2*)&raw;
#pragma unroll
        for (int i = 0; i < 4; i++) {
            float2 f = __half22float2(hp[i]);
            agg[2 * i] = swt * f.x;
            agg[2 * i + 1] = swt * f.y;
        }
    }
    int r1 = g_rowptr[v + 1];
    for (int j = g_rowptr[v]; j < r1; j++) {
        float w = g_w[j];
        int col = g_col[j];
        uint4 raw = *(const uint4*)(g_h1 + (size_t)col * 256 + t * 8);
        __half2* hp = (__half2*)&raw;
#pragma unroll
        for (int i = 0; i < 4; i++) {
            float2 f = __half22float2(hp[i]);
            agg[2 * i] += w * f.x;
            agg[2 * i + 1] += w * f.y;
        }
    }
    // partial matmul over my 8 k's, all 16 outputs
    float po[16];
#pragma unroll
    for (int c = 0; c < 16; c++) {
        float acc = 0.f;
#pragma unroll
        for (int i = 0; i < 8; i++) acc += agg[i] * sW[(h * 8 + i) * 16 + c];
        po[c] = acc;
    }
    // exchange partner partials (xor 1 swaps h within same batch)
    __half2 o[4];
#pragma unroll
    for (int i = 0; i < 4; i++) {
        int c0 = h * 8 + 2 * i, c1 = c0 + 1;
        int pc0 = (1 - h) * 8 + 2 * i, pc1 = pc0 + 1;
        float r0 = __shfl_xor_sync(0xFFFFFFFFu, po[pc0], 1);
        float r1v = __shfl_xor_sync(0xFFFFFFFFu, po[pc1], 1);
        float t0 = po[c0] + r0 + sb[c0];
        float t1 = po[c1] + r1v + sb[c1];
        t0 = t0 > 0.f ? t0 : 0.01f * t0;
        t1 = t1 > 0.f ? t1 : 0.01f * t1;
        o[i] = __floats2half2_rn(t0, t1);
    }
    *(uint4*)(g_h2 + (size_t)v * 256 + t * 8) = *(uint4*)o;
}

// Layer 3: h2 -> offs(3); v = x + offs; writes d_out and g_v4 (b,v layout).
__global__ void layer3_kernel(const float* __restrict__ x,
                              const float* __restrict__ W3,
                              const float* __restrict__ b3,
                              float* __restrict__ out, int V, int E) {
    __shared__ float sW[48], sb[3];
    if (threadIdx.x < 48) sW[threadIdx.x] = W3[threadIdx.x];
    if (threadIdx.x < 3) sb[threadIdx.x] = b3[threadIdx.x];
    __syncthreads();
    int v = blockIdx.x * 8 + (threadIdx.x >> 5);
    if (v >= V) return;
    int t = threadIdx.x & 31;
    int b = t >> 1, h = t & 1;
    float di = g_dinv[v];
    float swt = di * di;

    float agg[8];
    {
        uint4 raw = *(const uint4*)(g_h2 + (size_t)v * 256 + t * 8);
        __half2* hp = (__half2*)&raw;
#pragma unroll
        for (int i = 0; i < 4; i++) {
            float2 f = __half22float2(hp[i]);
            agg[2 * i] = swt * f.x;
            agg[2 * i + 1] = swt * f.y;
        }
    }
    int r1 = g_rowptr[v + 1];
    for (int j = g_rowptr[v]; j < r1; j++) {
        float w = g_w[j];
        int col = g_col[j];
        uint4 raw = *(const uint4*)(g_h2 + (size_t)col * 256 + t * 8);
        __half2* hp = (__half2*)&raw;
#pragma unroll
        for (int i = 0; i < 4; i++) {
            float2 f = __half22float2(hp[i]);
            agg[2 * i] += w * f.x;
            agg[2 * i + 1] += w * f.y;
        }
    }
    float po[3];
#pragma unroll
    for (int p = 0; p < 3; p++) {
        float acc = 0.f;
#pragma unroll
        for (int i = 0; i < 8; i++) acc += agg[i] * sW[(h * 8 + i) * 3 + p];
        po[p] = acc;
    }
    float offs[3];
#pragma unroll
    for (int p = 0; p < 3; p++)
        offs[p] = po[p] + __shfl_xor_sync(0xFFFFFFFFu, po[p], 1) + sb[p];

    if (h == 0) {
        size_t n = (size_t)b * V + v;
        const float* xr = x + n * 3;  // fp32 original verts (output-critical)
        float vx = offs[0] + xr[0];
        float vy = offs[1] + xr[1];
        float vz = offs[2] + xr[2];
        size_t o = ((size_t)b * (V + E) + v) * 3;
        out[o + 0] = vx;
        out[o + 1] = vy;
        out[o + 2] = vz;
        g_v4[n] = make_float4(vx, vy, vz, 0.f);
    }
}

// Midpoints: mid[b][e] = (v[b][src] + v[b][dst]) / 2. 2D grid, float4 gathers.
__global__ void mid_kernel(const int* __restrict__ edges, float* __restrict__ out,
                           int V, int E) {
    int e = blockIdx.x * blockDim.x + threadIdx.x;
    if (e >= E) return;
    int b = blockIdx.y;
    int2 sd = *(const int2*)(edges + 2 * e);
    int base = b * V;
    float4 vs = g_v4[base + sd.x];
    float4 vd = g_v4[base + sd.y];
    float* m = out + ((size_t)b * (V + E) + V + (size_t)e) * 3;
    m[0] = 0.5f * (vs.x + vd.x);
    m[1] = 0.5f * (vs.y + vd.y);
    m[2] = 0.5f * (vs.z + vd.z);
}

// Broadcast faces across B (float4-vectorized; exact below 2^24).
__global__ void faces_kernel(const int* __restrict__ faces, float* __restrict__ out,
                             int perB, int B) {
    int i4 = blockIdx.x * blockDim.x + threadIdx.x;
    int n4 = perB >> 2;
    if (i4 < n4) {
        int4 f = ((const int4*)faces)[i4];
        float4 vf = make_float4((float)f.x, (float)f.y, (float)f.z, (float)f.w);
#pragma unroll
        for (int b = 0; b < MAXB; b++)
            if (b < B) ((float4*)(out + (size_t)b * perB))[i4] = vf;
    } else {
        int i = (n4 << 2) + (i4 - n4);  // scalar tail
        if (i < perB) {
            float vf = (float)faces[i];
            for (int b = 0; b < B; b++) out[(size_t)b * perB + i] = vf;
        }
    }
}

extern "C" void kernel_launch(void* const* d_in, const int* in_sizes, int n_in,
                              void* d_out, int out_size) {
    const float* verts = (const float*)d_in[0];
    const int*   edges = (const int*)d_in[1];
    const int*   faces = (const int*)d_in[2];
    const float* W1 = (const float*)d_in[3];
    const float* b1 = (const float*)d_in[4];
    const float* W2 = (const float*)d_in[5];
    const float* b2 = (const float*)d_in[6];
    const float* W3 = (const float*)d_in[7];
    const float* b3 = (const float*)d_in[8];
    float* out = (float*)d_out;

    const int B = 16;
    int E = in_sizes[1] / 2;
    int Fsub = in_sizes[2] / 3;
    int V = in_sizes[0] / (B * 3);
    int N = B * V;
    int nScanBlocks = (V + 1023) / 1024;

    // CSR build (per-batch graph identical; build once over V,E)
    zero_kernel<<<(V + 255) / 256, 256>>>(V);
    count_kernel<<<(E + 255) / 256, 256>>>(edges, E);
    scanA_kernel<<<nScanBlocks, 1024>>>(V);
    scanB_kernel<<<1, 128>>>(nScanBlocks, V);
    scanC_kernel<<<(V + 255) / 256, 256>>>(V);
    scatter_kernel<<<(E + 255) / 256, 256>>>(edges, E);
    padT_kernel<<<(N + 255) / 256, 256>>>(verts, V, N);

    // GCN layers: warp per vertex, all batches at once
    int vblocks = (V + 7) / 8;
    layer1_kernel<<<vblocks, 256>>>(W1, b1, V);
    layer2_kernel<<<vblocks, 256>>>(W2, b2, V);
    layer3_kernel<<<vblocks, 256>>>(verts, W3, b3, out, V, E);

    // Midpoints
    dim3 midGrid((E + 255) / 256, B);
    mid_kernel<<<midGrid, 256>>>(edges, out, V, E);

    // Faces broadcast
    long long vertsOut = (long long)B * (V + E) * 3;
    long long facesOut = (long long)B * Fsub * 3;
    if ((long long)out_size >= vertsOut + facesOut) {
        int perB = Fsub * 3;
        int n4 = perB / 4;
        int totalThreads = n4 + (perB - n4 * 4);
        faces_kernel<<<(totalThreads + 255) / 256, 256>>>(faces, out + vertsOut, perB, B);
    }
}

// round 7
// speedup vs baseline: 2.8618x; 1.0328x over previous
#include <cuda_runtime.h>
#include <cuda_fp16.h>

#define MAXV 100000
#define MAXE 300000
#define MAXB 16
#define MAXN (MAXB * MAXV)

// ---- scratch (static __device__ per harness rules) ----
__device__ int    g_cnt[MAXV];
__device__ int    g_cur[MAXV];
__device__ int    g_rowptr[MAXV + 1];
__device__ int    g_part[128];
__device__ int    g_col[MAXE];
__device__ float  g_w[MAXE];
__device__ float  g_dinv[MAXV];
__device__ __align__(16) __half g_xT[(size_t)MAXV * MAXB * 4];   // xT[v][b][0..3] half (8B/node)
__device__ float4 g_v4[MAXN];                                    // (b,v) displaced verts fp32
__device__ __align__(16) __half g_h1[(size_t)MAXV * MAXB * 16];  // h[v][b][c]
__device__ __align__(16) __half g_h2[(size_t)MAXV * MAXB * 16];

// ---------------- CSR build ----------------
__global__ void zero_kernel(int V) {
    int i = blockIdx.x * blockDim.x + threadIdx.x;
    if (i < V) { g_cnt[i] = 0; g_cur[i] = 0; }
}

__global__ void count_kernel(const int* __restrict__ edges, int E) {
    int e = blockIdx.x * blockDim.x + threadIdx.x;
    if (e < E) atomicAdd(&g_cnt[edges[2 * e + 1]], 1);
}

// scanA also produces dinv (reads g_cnt anyway)
__global__ void scanA_kernel(int V) {
    __shared__ int sh[1024];
    int t = threadIdx.x;
    int i = blockIdx.x * 1024 + t;
    int val = (i < V) ? g_cnt[i] : 0;
    if (i < V) g_dinv[i] = rsqrtf((float)val + 1.0f);  // +1 self-loop
    sh[t] = val;
    __syncthreads();
    for (int off = 1; off < 1024; off <<= 1) {
        int add = (t >= off) ? sh[t - off] : 0;
        __syncthreads();
        sh[t] += add;
        __syncthreads();
    }
    if (i < V) g_rowptr[i] = sh[t] - val;
    if (t == 1023) g_part[blockIdx.x] = sh[1023];
}

__global__ void scanB_kernel(int nblocks, int V) {
    __shared__ int sh[128];
    int t = threadIdx.x;
    int val = (t < nblocks) ? g_part[t] : 0;
    sh[t] = val;
    __syncthreads();
    for (int off = 1; off < 128; off <<= 1) {
        int add = (t >= off) ? sh[t - off] : 0;
        __syncthreads();
        sh[t] += add;
        __syncthreads();
    }
    g_part[t] = sh[t] - val;
    if (t == 127) g_rowptr[V] = sh[127];
}

__global__ void scanC_kernel(int V) {
    int i = blockIdx.x * blockDim.x + threadIdx.x;
    if (i < V) g_rowptr[i] += g_part[i >> 10];
}

__global__ void scatter_kernel(const int* __restrict__ edges, int E) {
    int e = blockIdx.x * blockDim.x + threadIdx.x;
    if (e < E) {
        int s = edges[2 * e];
        int d = edges[2 * e + 1];
        int pos = g_rowptr[d] + atomicAdd(&g_cur[d], 1);
        g_col[pos] = s;
        g_w[pos] = g_dinv[s] * g_dinv[d];
    }
}

// Transpose x(b,v,3) -> xT[v][b] packed half (8B per (v,b)).
__global__ void padT_kernel(const float* __restrict__ x, int V, int N) {
    int n = blockIdx.x * blockDim.x + threadIdx.x;
    if (n >= N) return;
    int v = n % V, b = n / V;
    const float* p = x + (size_t)n * 3;
    __half2* dst = (__half2*)(g_xT + ((size_t)v * MAXB + b) * 4);
    dst[0] = __floats2half2_rn(p[0], p[1]);
    dst[1] = __floats2half2_rn(p[2], 0.f);
}

// ---------------- GCN layers: warp per vertex, all 16 batches ----------------
// lane t = 2*b + h ; thread handles batch b, channels [8h, 8h+8)

// Layer 1: xT -> h1[v][b][c]. Chunk-4 prefetched gathers for MLP.
__global__ void layer1_kernel(const float* __restrict__ W1,
                              const float* __restrict__ b1, int V) {
    __shared__ float sW[48], sb[16];
    if (threadIdx.x < 48) sW[threadIdx.x] = W1[threadIdx.x];
    if (threadIdx.x < 16) sb[threadIdx.x] = b1[threadIdx.x];
    __syncthreads();
    int v = blockIdx.x * 8 + (threadIdx.x >> 5);
    if (v >= V) return;
    int t = threadIdx.x & 31;
    int b = t >> 1, h = t & 1;
    float di = __ldg(&g_dinv[v]);
    float swt = di * di;

    uint2 raw = *(const uint2*)(g_xT + ((size_t)v * MAXB + b) * 4);
    float2 f0 = __half22float2(*(__half2*)&raw.x);
    float2 f1 = __half22float2(*(__half2*)&raw.y);
    float a0 = swt * f0.x, a1 = swt * f0.y, a2 = swt * f1.x;

    int j = __ldg(&g_rowptr[v]);
    int r1 = __ldg(&g_rowptr[v + 1]);
    for (; j + 4 <= r1; j += 4) {
        int c0 = __ldg(&g_col[j]),     c1 = __ldg(&g_col[j + 1]);
        int c2 = __ldg(&g_col[j + 2]), c3 = __ldg(&g_col[j + 3]);
        float w0 = __ldg(&g_w[j]),     w1 = __ldg(&g_w[j + 1]);
        float w2 = __ldg(&g_w[j + 2]), w3 = __ldg(&g_w[j + 3]);
        uint2 ra = *(const uint2*)(g_xT + ((size_t)c0 * MAXB + b) * 4);
        uint2 rb = *(const uint2*)(g_xT + ((size_t)c1 * MAXB + b) * 4);
        uint2 rc = *(const uint2*)(g_xT + ((size_t)c2 * MAXB + b) * 4);
        uint2 rd = *(const uint2*)(g_xT + ((size_t)c3 * MAXB + b) * 4);
        float2 g0, g1;
        g0 = __half22float2(*(__half2*)&ra.x); g1 = __half22float2(*(__half2*)&ra.y);
        a0 += w0 * g0.x; a1 += w0 * g0.y; a2 += w0 * g1.x;
        g0 = __half22float2(*(__half2*)&rb.x); g1 = __half22float2(*(__half2*)&rb.y);
        a0 += w1 * g0.x; a1 += w1 * g0.y; a2 += w1 * g1.x;
        g0 = __half22float2(*(__half2*)&rc.x); g1 = __half22float2(*(__half2*)&rc.y);
        a0 += w2 * g0.x; a1 += w2 * g0.y; a2 += w2 * g1.x;
        g0 = __half22float2(*(__half2*)&rd.x); g1 = __half22float2(*(__half2*)&rd.y);
        a0 += w3 * g0.x; a1 += w3 * g0.y; a2 += w3 * g1.x;
    }
    for (; j < r1; j++) {
        float w = __ldg(&g_w[j]);
        int col = __ldg(&g_col[j]);
        uint2 nb = *(const uint2*)(g_xT + ((size_t)col * MAXB + b) * 4);
        float2 g0 = __half22float2(*(__half2*)&nb.x);
        float2 g1 = __half22float2(*(__half2*)&nb.y);
        a0 += w * g0.x; a1 += w * g0.y; a2 += w * g1.x;
    }
    __half2 o[4];
#pragma unroll
    for (int i = 0; i < 4; i++) {
        int c0 = h * 8 + 2 * i, c1 = c0 + 1;
        float t0 = sb[c0] + a0 * sW[c0] + a1 * sW[16 + c0] + a2 * sW[32 + c0];
        float t1 = sb[c1] + a0 * sW[c1] + a1 * sW[16 + c1] + a2 * sW[32 + c1];
        t0 = t0 > 0.f ? t0 : 0.01f * t0;
        t1 = t1 > 0.f ? t1 : 0.01f * t1;
        o[i] = __floats2half2_rn(t0, t1);
    }
    *(uint4*)(g_h1 + (size_t)v * 256 + t * 8) = *(uint4*)o;  // 512B coalesced per warp
}

// Accumulate one 32B row (uint4 of half2) into agg[8] with weight w.
__device__ __forceinline__ void acc_row(float* agg, uint4 raw, float w) {
    __half2* hp = (__half2*)&raw;
#pragma unroll
    for (int i = 0; i < 4; i++) {
        float2 f = __half22float2(hp[i]);
        agg[2 * i] += w * f.x;
        agg[2 * i + 1] += w * f.y;
    }
}

// Gather loop with chunk-4 MLP over a half feature array laid out [v][256].
__device__ __forceinline__ void gather_agg(const __half* __restrict__ src,
                                           float* agg, int v, int t, float swt) {
    {
        uint4 raw = *(const uint4*)(src + (size_t)v * 256 + t * 8);
        __half2* hp = (__half2*)&raw;
#pragma unroll
        for (int i = 0; i < 4; i++) {
            float2 f = __half22float2(hp[i]);
            agg[2 * i] = swt * f.x;
            agg[2 * i + 1] = swt * f.y;
        }
    }
    int j = __ldg(&g_rowptr[v]);
    int r1 = __ldg(&g_rowptr[v + 1]);
    for (; j + 4 <= r1; j += 4) {
        int c0 = __ldg(&g_col[j]),     c1 = __ldg(&g_col[j + 1]);
        int c2 = __ldg(&g_col[j + 2]), c3 = __ldg(&g_col[j + 3]);
        float w0 = __ldg(&g_w[j]),     w1 = __ldg(&g_w[j + 1]);
        float w2 = __ldg(&g_w[j + 2]), w3 = __ldg(&g_w[j + 3]);
        uint4 ra = *(const uint4*)(src + (size_t)c0 * 256 + t * 8);
        uint4 rb = *(const uint4*)(src + (size_t)c1 * 256 + t * 8);
        uint4 rc = *(const uint4*)(src + (size_t)c2 * 256 + t * 8);
        uint4 rd = *(const uint4*)(src + (size_t)c3 * 256 + t * 8);
        acc_row(agg, ra, w0);
        acc_row(agg, rb, w1);
        acc_row(agg, rc, w2);
        acc_row(agg, rd, w3);
    }
    for (; j < r1; j++) {
        float w = __ldg(&g_w[j]);
        int col = __ldg(&g_col[j]);
        uint4 raw = *(const uint4*)(src + (size_t)col * 256 + t * 8);
        acc_row(agg, raw, w);
    }
}

// Layer 2: h1 -> h2.
__global__ void layer2_kernel(const float* __restrict__ W2,
                              const float* __restrict__ b2, int V) {
    __shared__ float sW[256], sb[16];
    sW[threadIdx.x] = W2[threadIdx.x];
    if (threadIdx.x < 16) sb[threadIdx.x] = b2[threadIdx.x];
    __syncthreads();
    int v = blockIdx.x * 8 + (threadIdx.x >> 5);
    if (v >= V) return;
    int t = threadIdx.x & 31;
    int h = t & 1;
    float di = __ldg(&g_dinv[v]);
    float agg[8];
    gather_agg(g_h1, agg, v, t, di * di);

    float po[16];
#pragma unroll
    for (int c = 0; c < 16; c++) {
        float acc = 0.f;
#pragma unroll
        for (int i = 0; i < 8; i++) acc += agg[i] * sW[(h * 8 + i) * 16 + c];
        po[c] = acc;
    }
    __half2 o[4];
#pragma unroll
    for (int i = 0; i < 4; i++) {
        int c0 = h * 8 + 2 * i, c1 = c0 + 1;
        int pc0 = (1 - h) * 8 + 2 * i, pc1 = pc0 + 1;
        float r0 = __shfl_xor_sync(0xFFFFFFFFu, po[pc0], 1);
        float r1v = __shfl_xor_sync(0xFFFFFFFFu, po[pc1], 1);
        float t0 = po[c0] + r0 + sb[c0];
        float t1 = po[c1] + r1v + sb[c1];
        t0 = t0 > 0.f ? t0 : 0.01f * t0;
        t1 = t1 > 0.f ? t1 : 0.01f * t1;
        o[i] = __floats2half2_rn(t0, t1);
    }
    *(uint4*)(g_h2 + (size_t)v * 256 + t * 8) = *(uint4*)o;
}

// Layer 3: h2 -> offs(3); v = x + offs; writes d_out and g_v4 (b,v layout).
__global__ void layer3_kernel(const float* __restrict__ x,
                              const float* __restrict__ W3,
                              const float* __restrict__ b3,
                              float* __restrict__ out, int V, int E) {
    __shared__ float sW[48], sb[3];
    if (threadIdx.x < 48) sW[threadIdx.x] = W3[threadIdx.x];
    if (threadIdx.x < 3) sb[threadIdx.x] = b3[threadIdx.x];
    __syncthreads();
    int v = blockIdx.x * 8 + (threadIdx.x >> 5);
    if (v >= V) return;
    int t = threadIdx.x & 31;
    int b = t >> 1, h = t & 1;
    float di = __ldg(&g_dinv[v]);
    float agg[8];
    gather_agg(g_h2, agg, v, t, di * di);

    float po[3];
#pragma unroll
    for (int p = 0; p < 3; p++) {
        float acc = 0.f;
#pragma unroll
        for (int i = 0; i < 8; i++) acc += agg[i] * sW[(h * 8 + i) * 3 + p];
        po[p] = acc;
    }
    float offs[3];
#pragma unroll
    for (int p = 0; p < 3; p++)
        offs[p] = po[p] + __shfl_xor_sync(0xFFFFFFFFu, po[p], 1) + sb[p];

    if (h == 0) {
        size_t n = (size_t)b * V + v;
        const float* xr = x + n * 3;  // fp32 original verts (output-critical)
        float vx = offs[0] + xr[0];
        float vy = offs[1] + xr[1];
        float vz = offs[2] + xr[2];
        size_t o = ((size_t)b * (V + E) + v) * 3;
        out[o + 0] = vx;
        out[o + 1] = vy;
        out[o + 2] = vz;
        g_v4[n] = make_float4(vx, vy, vz, 0.f);
    }
}

// Midpoints: mid[b][e] = (v[b][src] + v[b][dst]) / 2. 2D grid, float4 gathers.
__global__ void mid_kernel(const int* __restrict__ edges, float* __restrict__ out,
                           int V, int E) {
    int e = blockIdx.x * blockDim.x + threadIdx.x;
    if (e >= E) return;
    int b = blockIdx.y;
    int2 sd = *(const int2*)(edges + 2 * e);
    int base = b * V;
    float4 vs = g_v4[base + sd.x];
    float4 vd = g_v4[base + sd.y];
    float* m = out + ((size_t)b * (V + E) + V + (size_t)e) * 3;
    m[0] = 0.5f * (vs.x + vd.x);
    m[1] = 0.5f * (vs.y + vd.y);
    m[2] = 0.5f * (vs.z + vd.z);
}

// Broadcast faces across B (float4-vectorized; exact below 2^24).
__global__ void faces_kernel(const int* __restrict__ faces, float* __restrict__ out,
                             int perB, int B) {
    int i4 = blockIdx.x * blockDim.x + threadIdx.x;
    int n4 = perB >> 2;
    if (i4 < n4) {
        int4 f = ((const int4*)faces)[i4];
        float4 vf = make_float4((float)f.x, (float)f.y, (float)f.z, (float)f.w);
#pragma unroll
        for (int b = 0; b < MAXB; b++)
            if (b < B) ((float4*)(out + (size_t)b * perB))[i4] = vf;
    } else {
        int i = (n4 << 2) + (i4 - n4);  // scalar tail
        if (i < perB) {
            float vf = (float)faces[i];
            for (int b = 0; b < B; b++) out[(size_t)b * perB + i] = vf;
        }
    }
}

extern "C" void kernel_launch(void* const* d_in, const int* in_sizes, int n_in,
                              void* d_out, int out_size) {
    const float* verts = (const float*)d_in[0];
    const int*   edges = (const int*)d_in[1];
    const int*   faces = (const int*)d_in[2];
    const float* W1 = (const float*)d_in[3];
    const float* b1 = (const float*)d_in[4];
    const float* W2 = (const float*)d_in[5];
    const float* b2 = (const float*)d_in[6];
    const float* W3 = (const float*)d_in[7];
    const float* b3 = (const float*)d_in[8];
    float* out = (float*)d_out;

    const int B = 16;
    int E = in_sizes[1] / 2;
    int Fsub = in_sizes[2] / 3;
    int V = in_sizes[0] / (B * 3);
    int N = B * V;
    int nScanBlocks = (V + 1023) / 1024;

    // CSR build (per-batch graph identical; build once over V,E)
    zero_kernel<<<(V + 255) / 256, 256>>>(V);
    count_kernel<<<(E + 255) / 256, 256>>>(edges, E);
    scanA_kernel<<<nScanBlocks, 1024>>>(V);
    scanB_kernel<<<1, 128>>>(nScanBlocks, V);
    scanC_kernel<<<(V + 255) / 256, 256>>>(V);
    scatter_kernel<<<(E + 255) / 256, 256>>>(edges, E);
    padT_kernel<<<(N + 255) / 256, 256>>>(verts, V, N);

    // GCN layers: warp per vertex, all batches at once
    int vblocks = (V + 7) / 8;
    layer1_kernel<<<vblocks, 256>>>(W1, b1, V);
    layer2_kernel<<<vblocks, 256>>>(W2, b2, V);
    layer3_kernel<<<vblocks, 256>>>(verts, W3, b3, out, V, E);

    // Midpoints
    dim3 midGrid((E + 255) / 256, B);
    mid_kernel<<<midGrid, 256>>>(edges, out, V, E);

    // Faces broadcast
    long long vertsOut = (long long)B * (V + E) * 3;
    long long facesOut = (long long)B * Fsub * 3;
    if ((long long)out_size >= vertsOut + facesOut) {
        int perB = Fsub * 3;
        int n4 = perB / 4;
        int totalThreads = n4 + (perB - n4 * 4);
        faces_kernel<<<(totalThreads + 255) / 256, 256>>>(faces, out + vertsOut, perB, B);
    }
}